// round 1
// baseline (speedup 1.0000x reference)
#include <cuda_runtime.h>
#include <cuda_bf16.h>

// ROCModel: per-row weighted histogram (searchsorted into linspace(0,1,100)),
// suffix-sum ROC curves, derivative curves, trapz integrals.
//
// Strategy: 1 CTA per row, per-THREAD privatized shared-memory histograms
// (no atomics, conflict-free banking), exact bin computation matching JAX
// linspace boundaries via a lane-replicated t-table.

#define MBINS 100
#define TPB   128   // threads per block (multiple of 32)

__global__ __launch_bounds__(TPB)
void roc_kernel(const float* __restrict__ x,
                const float* __restrict__ y,
                float* __restrict__ out,
                int B, int N)
{
    extern __shared__ float smem[];
    float* hist = smem;                       // [MBINS][TPB]   per-thread private
    float* trep = smem + MBINS * TPB;         // [MBINS][32]    t replicated per lane
    float* bsum = trep + MBINS * 32;          // [MBINS]
    float* ssum = bsum + MBINS;               // [MBINS]
    float* tz   = ssum + MBINS;               // [2]

    const int tid  = threadIdx.x;
    const int lane = tid & 31;
    const int row  = blockIdx.x;

    // ---- init ----
    #pragma unroll
    for (int i = tid; i < MBINS * TPB; i += TPB) hist[i] = 0.0f;
    for (int e = tid; e < MBINS * 32; e += TPB) {
        int j = e >> 5;
        // JAX linspace(0,1,100): t[i] = fl(i/99) (RN), t[99] = 1.0 exactly
        trep[e] = (j == MBINS - 1) ? 1.0f : __fdiv_rn((float)j, (float)(MBINS - 1));
    }
    if (tid < 2) tz[tid] = 0.0f;
    __syncthreads();

    // ---- main histogram loop ----
    const float* xrow = x + (size_t)row * (size_t)N;
    const float4* xr4 = (const float4*)xrow;
    const int n4 = N >> 2;

    #define PROC(XV) do {                                                   \
        const float xv = (XV);                                              \
        int j = __float2int_ru(__fmul_rn(xv, (float)(MBINS - 1)));          \
        j = max(j, 1); j = min(j, MBINS - 1);                               \
        const float tlo = trep[((j - 1) << 5) | lane];                      \
        const float thi = trep[(j << 5) | lane];                            \
        if (thi < xv)        { j = min(j + 1, MBINS - 1); }                 \
        else if (tlo >= xv)  { j = j - 1; }                                 \
        const int a = j * TPB + tid;                                        \
        hist[a] += xv;                                                      \
    } while (0)

    #pragma unroll 4
    for (int i = tid; i < n4; i += TPB) {
        float4 v = xr4[i];
        PROC(v.x); PROC(v.y); PROC(v.z); PROC(v.w);
    }
    // scalar tail (N not multiple of 4)
    for (int i = (n4 << 2) + tid; i < N; i += TPB) PROC(xrow[i]);
    #undef PROC
    __syncthreads();

    // ---- reduce per-thread copies to per-bin totals (bank-swizzled, conflict-free) ----
    if (tid < MBINS) {
        const int b = tid;
        float s = 0.0f;
        #pragma unroll 8
        for (int t = 0; t < TPB; ++t)
            s += hist[b * TPB + ((t + b) & (TPB - 1))];
        bsum[b] = s;
    }
    __syncthreads();

    // ---- suffix sum: roc[j] = sum_{k>=j} full[k], full = [bsum[1..99], tail=0] ----
    if (tid == 0) {
        float acc = 0.0f;
        ssum[MBINS - 1] = 0.0f;          // tail is provably 0 (x < 1 <= t[99])
        for (int k = MBINS - 2; k >= 0; --k) {
            acc += bsum[k + 1];
            ssum[k] = acc;
        }
    }
    __syncthreads();

    // ---- outputs ----
    const float yv = y[row];
    if (tid < MBINS) {
        const int j = tid;
        const float r = __fdiv_rn(ssum[j], yv);
        const float d0 = (j < MBINS - 1)
                         ? bsum[j + 1]
                         : (bsum[MBINS - 1] + bsum[MBINS - 2]) * 0.5f;
        const float d = __fdiv_rn(d0, yv);

        out[(size_t)row * MBINS + j] = r;
        out[(size_t)B * MBINS + (size_t)row * MBINS + j] = d;

        // trapz(f) = 0.5*f[0] + f[1..98] + 0.5*f[99]
        const float w = (j == 0 || j == MBINS - 1) ? 0.5f : 1.0f;
        atomicAdd(&tz[0], w * r);
        atomicAdd(&tz[1], w * d);
    }
    __syncthreads();
    if (tid == 0) {
        const size_t base = (size_t)2 * (size_t)B * MBINS;
        out[base + row]              = tz[0];
        out[base + (size_t)B + row]  = tz[1];
    }
}

extern "C" void kernel_launch(void* const* d_in, const int* in_sizes, int n_in,
                              void* d_out, int out_size)
{
    const float* x = (const float*)d_in[0];
    const float* y = (const float*)d_in[1];
    const int B = in_sizes[1];
    const int N = in_sizes[0] / B;

    const size_t smem_bytes = (size_t)(MBINS * TPB + MBINS * 32 + 2 * MBINS + 2) * sizeof(float);
    cudaFuncSetAttribute(roc_kernel, cudaFuncAttributeMaxDynamicSharedMemorySize,
                         (int)smem_bytes);
    roc_kernel<<<B, TPB, smem_bytes>>>(x, y, (float*)d_out, B, N);
}

// round 4
// speedup vs baseline: 1.6211x; 1.6211x over previous
#include <cuda_runtime.h>
#include <cuda_bf16.h>

// ROCModel: per-row weighted histogram (searchsorted into linspace(0,1,100)),
// suffix-sum ROC curves, derivative curves, trapz integrals.
//
// R4: same MLP theory as R2/R3 (raise in-flight LDG.128 per warp from ~4 to
// ~8-16 to cover DRAM latency), simpler realization: single rolling prefetch
// buffer, plain loops instead of macro pipeline, no minBlocks launch bound.

#define MBINS 100
#define TPB   128
#define CHUNK 8          // float4 per thread per chunk

__global__ __launch_bounds__(TPB)
void roc_kernel(const float* __restrict__ x,
                const float* __restrict__ y,
                float* __restrict__ out,
                int B, int N)
{
    extern __shared__ float smem[];
    float* hist = smem;                       // [MBINS][TPB] per-thread private
    float* trep = smem + MBINS * TPB;         // [MBINS][32]  t replicated per lane
    float* bsum = trep + MBINS * 32;          // [MBINS]
    float* ssum = bsum + MBINS;               // [MBINS]
    float* tz   = ssum + MBINS;               // [2]

    const int tid  = threadIdx.x;
    const int lane = tid & 31;
    const int row  = blockIdx.x;

    // ---- init ----
    for (int i = tid; i < MBINS * TPB; i += TPB) hist[i] = 0.0f;
    for (int e = tid; e < MBINS * 32; e += TPB) {
        int j = e >> 5;
        // JAX linspace(0,1,100): t[i] = fl(i/99) (RN), t[99] = 1.0 exactly
        trep[e] = (j == MBINS - 1) ? 1.0f : __fdiv_rn((float)j, (float)(MBINS - 1));
    }
    if (tid < 2) tz[tid] = 0.0f;
    __syncthreads();

    const float* xrow = x + (size_t)row * (size_t)N;
    const float4* xr4 = (const float4*)xrow;
    const int n4 = N >> 2;

    const float* tlane = trep + lane;         // this lane's t replica base
    float* hbase = hist + tid;                // this thread's hist column

    // Exact bin: c = #{i in 0..99 : t[i] < x}. g = floor(fl(99*x)) is within
    // 1 ulp of the true cell, so checking t[g], t[g+1] suffices. g<=98.
    auto proc = [&](float xv) {
        int g = __float2int_rd(__fmul_rn(xv, (float)(MBINS - 1)));
        g = min(g, MBINS - 2);
        const float t0 = tlane[g << 5];
        const float t1 = tlane[(g << 5) + 32];
        const int c = g + (t0 < xv) + (t1 < xv);
        hbase[c * TPB] += xv;
    };

    const int STEP  = CHUNK * TPB;            // float4s consumed per chunk
    const int nfull = n4 / STEP;

    if (nfull > 0) {
        float4 buf[CHUNK];
        int base = tid;
        // prime
        #pragma unroll
        for (int k = 0; k < CHUNK; ++k) buf[k] = xr4[base + k * TPB];
        base += STEP;

        for (int c = 1; c < nfull; ++c) {
            float4 nxt[CHUNK];
            #pragma unroll
            for (int k = 0; k < CHUNK; ++k) nxt[k] = xr4[base + k * TPB];
            base += STEP;
            #pragma unroll
            for (int k = 0; k < CHUNK; ++k) {
                proc(buf[k].x); proc(buf[k].y); proc(buf[k].z); proc(buf[k].w);
            }
            #pragma unroll
            for (int k = 0; k < CHUNK; ++k) buf[k] = nxt[k];
        }
        #pragma unroll
        for (int k = 0; k < CHUNK; ++k) {
            proc(buf[k].x); proc(buf[k].y); proc(buf[k].z); proc(buf[k].w);
        }
    }

    // leftover float4s
    for (int i = nfull * STEP + tid; i < n4; i += TPB) {
        float4 v = xr4[i];
        proc(v.x); proc(v.y); proc(v.z); proc(v.w);
    }
    // scalar tail
    for (int i = (n4 << 2) + tid; i < N; i += TPB) proc(xrow[i]);
    __syncthreads();

    // ---- reduce per-thread copies to per-bin totals (bank-swizzled) ----
    if (tid < MBINS) {
        const int b = tid;
        float s = 0.0f;
        #pragma unroll 8
        for (int t = 0; t < TPB; ++t)
            s += hist[b * TPB + ((t + b) & (TPB - 1))];
        bsum[b] = s;
    }
    __syncthreads();

    // ---- suffix sum: roc[j] = sum_{k>=j} full[k], full = [bsum[1..99], 0] ----
    if (tid == 0) {
        float acc = 0.0f;
        ssum[MBINS - 1] = 0.0f;               // tail provably 0 (x < 1 <= t[99])
        for (int k = MBINS - 2; k >= 0; --k) {
            acc += bsum[k + 1];
            ssum[k] = acc;
        }
    }
    __syncthreads();

    // ---- outputs ----
    const float yv = y[row];
    if (tid < MBINS) {
        const int j = tid;
        const float r = __fdiv_rn(ssum[j], yv);
        const float d0 = (j < MBINS - 1)
                         ? bsum[j + 1]
                         : (bsum[MBINS - 1] + bsum[MBINS - 2]) * 0.5f;
        const float d = __fdiv_rn(d0, yv);

        out[(size_t)row * MBINS + j] = r;
        out[(size_t)B * MBINS + (size_t)row * MBINS + j] = d;

        const float w = (j == 0 || j == MBINS - 1) ? 0.5f : 1.0f;
        atomicAdd(&tz[0], w * r);
        atomicAdd(&tz[1], w * d);
    }
    __syncthreads();
    if (tid == 0) {
        const size_t base2 = (size_t)2 * (size_t)B * MBINS;
        out[base2 + row]             = tz[0];
        out[base2 + (size_t)B + row] = tz[1];
    }
}

extern "C" void kernel_launch(void* const* d_in, const int* in_sizes, int n_in,
                              void* d_out, int out_size)
{
    const float* x = (const float*)d_in[0];
    const float* y = (const float*)d_in[1];
    const int B = in_sizes[1];
    const int N = in_sizes[0] / B;

    const size_t smem_bytes = (size_t)(MBINS * TPB + MBINS * 32 + 2 * MBINS + 2) * sizeof(float);
    cudaFuncSetAttribute(roc_kernel, cudaFuncAttributeMaxDynamicSharedMemorySize,
                         (int)smem_bytes);
    roc_kernel<<<B, TPB, smem_bytes>>>(x, y, (float*)d_out, B, N);
}